// round 17
// baseline (speedup 1.0000x reference)
#include <cuda_runtime.h>
#include <cuda_bf16.h>
#include <cuda_fp16.h>
#include <math.h>
#include <mma.h>

using namespace nvcuda;

// Problem constants
#define NN    50000
#define NPAD  50176            // 784*64 row tiles; 1024*49 for the scan
#define EE    1600000
#define HDIM  128

// ---------------- static device scratch (allocation-free) ----------------
__device__ __align__(16) int   g_icnt[NPAD];
__device__ __align__(16) int   g_rowptr[NPAD + 1];
__device__ __align__(16) int   g_cur[NPAD];
__device__ __align__(16) int2  g_csr[EE];           // {src, norm-bits} grouped by dst
__device__ __align__(16) float g_dis[NPAD];
__device__ __align__(16) __half g_hg16[(size_t)NPAD * HDIM]; // fp16 hg (layer gather)
__device__ __align__(16) float g_agg[(size_t)NPAD * HDIM];
// bf16 hi/lo operand images
__device__ __align__(16) __nv_bfloat16 g_ahi[(size_t)NPAD * HDIM];
__device__ __align__(16) __nv_bfloat16 g_alo[(size_t)NPAD * HDIM];
// weight slots: slot 0 = W_pre (cols 0-127); slot 1+l = [gcn_W_l | skip_W_l] (256 cols)
__device__ __align__(16) __nv_bfloat16 g_whi[(size_t)4 * HDIM * 256];
__device__ __align__(16) __nv_bfloat16 g_wlo[(size_t)4 * HDIM * 256];

// ---------------- math helpers ----------------
__device__ __forceinline__ float mishf(float x) {
    float sp = fmaxf(x, 0.0f) + log1pf(expf(-fabsf(x)));
    return x * tanhf(sp);
}
__device__ __forceinline__ void bsplit(float x, __nv_bfloat16& h, __nv_bfloat16& l) {
    h = __float2bfloat16_rn(x);
    l = __float2bfloat16_rn(x - __bfloat162float(h));
}
__device__ __forceinline__ void cp_async16(void* smem_dst, const void* gmem_src) {
    unsigned s = (unsigned)__cvta_generic_to_shared(smem_dst);
    asm volatile("cp.async.ca.shared.global [%0], [%1], 16;" :: "r"(s), "l"(gmem_src) : "memory");
}

// ---------------- CSR build ----------------
__global__ void zero_cnt_kernel(int n) {
    int i = blockIdx.x * blockDim.x + threadIdx.x;
    if (i < n) g_icnt[i] = 0;
}
__global__ void count_kernel(const int* __restrict__ ei, int e, int n) {
    int i = blockIdx.x * blockDim.x + threadIdx.x;
    if (i < e) {
        int d = ei[e + i];
        if ((unsigned)d >= (unsigned)n) d = 0;
        atomicAdd(&g_icnt[d], 1);
    }
}
__global__ void scan_kernel() {
    __shared__ int part[1024];
    const int CH = NPAD / 1024;            // 49
    int t = threadIdx.x;
    int base = t * CH;
    int sum = 0;
    for (int i = 0; i < CH; i++) sum += g_icnt[base + i];
    part[t] = sum;
    __syncthreads();
    for (int off = 1; off < 1024; off <<= 1) {
        int v = (t >= off) ? part[t - off] : 0;
        __syncthreads();
        part[t] += v;
        __syncthreads();
    }
    int run = part[t] - sum;
    for (int i = 0; i < CH; i++) {
        int c = g_icnt[base + i];
        g_rowptr[base + i] = run;
        g_cur[base + i]    = run;
        run += c;
    }
    if (t == 1023) g_rowptr[NPAD] = run;
}
__global__ void dis_kernel(int n) {
    int i = blockIdx.x * blockDim.x + threadIdx.x;
    if (i < n) g_dis[i] = rsqrtf(1.0f + (float)g_icnt[i]);
}
__global__ void scatter_kernel(const int* __restrict__ ei, int e, int n) {
    int i = blockIdx.x * blockDim.x + threadIdx.x;
    if (i < e) {
        int s = ei[i];
        int d = ei[e + i];
        if ((unsigned)s >= (unsigned)n) s = 0;
        if ((unsigned)d >= (unsigned)n) d = 0;
        float norm = g_dis[s] * g_dis[d];
        int pos = atomicAdd(&g_cur[d], 1);
        g_csr[pos] = make_int2(s, __float_as_int(norm));
    }
}

// ---------------- operand prep ----------------
__global__ void split_x_kernel(const float* __restrict__ x, int M, int ntot) {
    int i = blockIdx.x * blockDim.x + threadIdx.x;
    if (i >= ntot) return;
    int row = i >> 7;
    float v = (row < M) ? x[i] : 0.0f;
    bsplit(v, g_ahi[i], g_alo[i]);
}
__global__ void split_w_kernel(const float* __restrict__ W, int slot, int colOff) {
    int i = blockIdx.x * blockDim.x + threadIdx.x;
    if (i >= HDIM * HDIM) return;
    int r = i >> 7, c = i & 127;
    size_t o = (size_t)slot * HDIM * 256 + (size_t)r * 256 + colOff + c;
    bsplit(W[i], g_whi[o], g_wlo[o]);
}

// ---------------- wmma bf16 3-term GEMM, 64-row x 128-col tiles, 2 CTAs/SM --------
// MODE 0 (pre):  blockIdx.y==0; epilogue = mish(acc + b_pre) -> g_ahi/g_alo splits
// MODE 1 (layer): blockIdx.y==0 -> gcn cols  -> g_hg16 (fp16 via smem staging)
//                 blockIdx.y==1 -> skip cols -> g_agg fp32 (direct store)
#define LDA3 136
#define LDB3 136
#define ASZ64 (64 * LDA3)            // bf16 elems per A half
#define BSZ64 (128 * LDB3)           // bf16 elems per B half
#define SMEM64 ((2 * ASZ64 + 2 * BSZ64) * 2)   // 104448 B -> 2 CTAs/SM

template <int MODE>
__global__ __launch_bounds__(256, 2) void wmma_gemm64(int slot, const float* __restrict__ bias) {
    extern __shared__ __nv_bfloat16 sm[];
    __nv_bfloat16* Ah = sm;
    __nv_bfloat16* Al = sm + ASZ64;
    __nv_bfloat16* Bh = sm + 2 * ASZ64;
    __nv_bfloat16* Bl = sm + 2 * ASZ64 + BSZ64;
    // Epilogues reuse [Ah|Al] as a 64x132 fp32 staging buffer:
    static_assert(64 * 132 * 4 <= 2 * ASZ64 * 2, "fp32 staging must fit in Ah+Al");

    int tid = threadIdx.x;
    int warp = tid >> 5;
    int wm = warp & 3;                 // 4 row bands of 16
    int wn = warp >> 2;                // 2 col bands of 64
    int block_row = blockIdx.x * 64;
    int colHalf = (MODE == 1) ? blockIdx.y : 0;   // which 128-col half of the slot

    // Phase 0 fill: A cols 0-63, B rows 0-63
    for (int idx = tid; idx < 64 * 8; idx += 256) {
        int r = idx >> 3;
        int c8 = (idx & 7) << 3;
        size_t go = (size_t)(block_row + r) * HDIM + c8;
        cp_async16(&Ah[r * LDA3 + c8], g_ahi + go);
        cp_async16(&Al[r * LDA3 + c8], g_alo + go);
    }
    for (int idx = tid; idx < 64 * 16; idx += 256) {
        int r = idx >> 4;
        int c8 = (idx & 15) << 3;
        size_t go = (size_t)slot * HDIM * 256 + (size_t)r * 256 + colHalf * 128 + c8;
        cp_async16(&Bh[r * LDB3 + c8], g_whi + go);
        cp_async16(&Bl[r * LDB3 + c8], g_wlo + go);
    }
    asm volatile("cp.async.commit_group;" ::: "memory");
    // Phase 1 fill: A cols 64-127, B rows 64-127
    for (int idx = tid; idx < 64 * 8; idx += 256) {
        int r = idx >> 3;
        int c8 = ((idx & 7) << 3) + 64;
        size_t go = (size_t)(block_row + r) * HDIM + c8;
        cp_async16(&Ah[r * LDA3 + c8], g_ahi + go);
        cp_async16(&Al[r * LDA3 + c8], g_alo + go);
    }
    for (int idx = tid; idx < 64 * 16; idx += 256) {
        int r = 64 + (idx >> 4);
        int c8 = (idx & 15) << 3;
        size_t go = (size_t)slot * HDIM * 256 + (size_t)r * 256 + colHalf * 128 + c8;
        cp_async16(&Bh[r * LDB3 + c8], g_whi + go);
        cp_async16(&Bl[r * LDB3 + c8], g_wlo + go);
    }
    asm volatile("cp.async.commit_group;" ::: "memory");

    wmma::fragment<wmma::accumulator, 16, 16, 16, float> acc[4];
#pragma unroll
    for (int j = 0; j < 4; j++) wmma::fill_fragment(acc[j], 0.0f);

    int cbase = wn * 64;

    asm volatile("cp.async.wait_group 1;" ::: "memory");
    __syncthreads();
#pragma unroll
    for (int k = 0; k < 4; k++) {
        wmma::fragment<wmma::matrix_a, 16, 16, 16, __nv_bfloat16, wmma::row_major> ah, al;
        wmma::fragment<wmma::matrix_b, 16, 16, 16, __nv_bfloat16, wmma::row_major> bh[4], bl[4];
        wmma::load_matrix_sync(ah, &Ah[(wm * 16) * LDA3 + k * 16], LDA3);
        wmma::load_matrix_sync(al, &Al[(wm * 16) * LDA3 + k * 16], LDA3);
#pragma unroll
        for (int j = 0; j < 4; j++) {
            wmma::load_matrix_sync(bh[j], &Bh[(k * 16) * LDB3 + cbase + j * 16], LDB3);
            wmma::load_matrix_sync(bl[j], &Bl[(k * 16) * LDB3 + cbase + j * 16], LDB3);
        }
#pragma unroll
        for (int j = 0; j < 4; j++) {
            wmma::mma_sync(acc[j], ah, bh[j], acc[j]);
            wmma::mma_sync(acc[j], ah, bl[j], acc[j]);
            wmma::mma_sync(acc[j], al, bh[j], acc[j]);
        }
    }
    asm volatile("cp.async.wait_group 0;" ::: "memory");
    __syncthreads();
#pragma unroll
    for (int k = 4; k < 8; k++) {
        wmma::fragment<wmma::matrix_a, 16, 16, 16, __nv_bfloat16, wmma::row_major> ah, al;
        wmma::fragment<wmma::matrix_b, 16, 16, 16, __nv_bfloat16, wmma::row_major> bh[4], bl[4];
        wmma::load_matrix_sync(ah, &Ah[(wm * 16) * LDA3 + k * 16], LDA3);
        wmma::load_matrix_sync(al, &Al[(wm * 16) * LDA3 + k * 16], LDA3);
#pragma unroll
        for (int j = 0; j < 4; j++) {
            wmma::load_matrix_sync(bh[j], &Bh[(k * 16) * LDB3 + cbase + j * 16], LDB3);
            wmma::load_matrix_sync(bl[j], &Bl[(k * 16) * LDB3 + cbase + j * 16], LDB3);
        }
#pragma unroll
        for (int j = 0; j < 4; j++) {
            wmma::mma_sync(acc[j], ah, bh[j], acc[j]);
            wmma::mma_sync(acc[j], ah, bl[j], acc[j]);
            wmma::mma_sync(acc[j], al, bh[j], acc[j]);
        }
    }

    if (MODE == 1 && colHalf == 1) {
        // skip branch: direct fp32 store to g_agg
#pragma unroll
        for (int j = 0; j < 4; j++)
            wmma::store_matrix_sync(
                g_agg + (size_t)(block_row + wm * 16) * HDIM + cbase + j * 16,
                acc[j], HDIM, wmma::mem_row_major);
        return;
    }

    // stage fp32 tile in smem (reuses A region)
    float* Sf = reinterpret_cast<float*>(sm);   // 64 x 132
    __syncthreads();
#pragma unroll
    for (int j = 0; j < 4; j++)
        wmma::store_matrix_sync(&Sf[(wm * 16) * 132 + cbase + j * 16], acc[j], 132,
                                wmma::mem_row_major);
    __syncthreads();

    if (MODE == 0) {
        // fused preprocess: mish(acc + b_pre) -> bf16 hi/lo splits
        for (int idx = tid; idx < 64 * 32; idx += 256) {
            int r = idx >> 5;
            int c4 = (idx & 31) << 2;
            float4 t = *reinterpret_cast<float4*>(&Sf[r * 132 + c4]);
            float4 b = *reinterpret_cast<const float4*>(bias + c4);
            size_t fo = (size_t)(block_row + r) * HDIM + c4;
            float o0 = mishf(t.x + b.x), o1 = mishf(t.y + b.y);
            float o2 = mishf(t.z + b.z), o3 = mishf(t.w + b.w);
            __nv_bfloat16 h4[4], l4[4];
            bsplit(o0, h4[0], l4[0]);
            bsplit(o1, h4[1], l4[1]);
            bsplit(o2, h4[2], l4[2]);
            bsplit(o3, h4[3], l4[3]);
            *reinterpret_cast<uint2*>(g_ahi + fo) = *reinterpret_cast<uint2*>(h4);
            *reinterpret_cast<uint2*>(g_alo + fo) = *reinterpret_cast<uint2*>(l4);
        }
    } else {
        // gcn branch: fp16 convert -> g_hg16
        for (int idx = tid; idx < 64 * 16; idx += 256) {
            int r = idx >> 4;
            int c8 = (idx & 15) << 3;
            float4 v0 = *reinterpret_cast<float4*>(&Sf[r * 132 + c8]);
            float4 v1 = *reinterpret_cast<float4*>(&Sf[r * 132 + c8 + 4]);
            __half2 hh[4];
            hh[0] = __floats2half2_rn(v0.x, v0.y);
            hh[1] = __floats2half2_rn(v0.z, v0.w);
            hh[2] = __floats2half2_rn(v1.x, v1.y);
            hh[3] = __floats2half2_rn(v1.z, v1.w);
            *reinterpret_cast<uint4*>(g_hg16 + (size_t)(block_row + r) * HDIM + c8) =
                *reinterpret_cast<uint4*>(hh);
        }
    }
}

// ---------------- CSR pull aggregation (fp16 gather) + biases + self-loop + mish ---
// LAST=false: h -> bf16 hi/lo splits; LAST=true: fused post matvec
template <bool LAST>
__global__ __launch_bounds__(256) void csr_agg_kernel(const float* __restrict__ gb,
                                                      const float* __restrict__ sb,
                                                      const float* __restrict__ Wp,
                                                      const float* __restrict__ bp,
                                                      float* __restrict__ out, int M) {
    int warp = (blockIdx.x * blockDim.x + threadIdx.x) >> 5;
    int lane = threadIdx.x & 31;
    if (warp >= NPAD) return;
    if (LAST && warp >= M) return;

    float4 acc = *reinterpret_cast<const float4*>(g_agg + (size_t)warp * HDIM + lane * 4);
    {
        float4 b1 = *reinterpret_cast<const float4*>(gb + lane * 4);
        float4 b2 = *reinterpret_cast<const float4*>(sb + lane * 4);
        uint2 u = *reinterpret_cast<const uint2*>(g_hg16 + (size_t)warp * HDIM + lane * 4);
        float2 f0 = __half22float2(*reinterpret_cast<__half2*>(&u.x));
        float2 f1 = __half22float2(*reinterpret_cast<__half2*>(&u.y));
        float dis = g_dis[warp];
        float d2 = dis * dis;
        acc.x += b1.x + b2.x + d2 * f0.x;
        acc.y += b1.y + b2.y + d2 * f0.y;
        acc.z += b1.z + b2.z + d2 * f1.x;
        acc.w += b1.w + b2.w + d2 * f1.y;
    }
    int base = g_rowptr[warp];
    int end  = g_rowptr[warp + 1];

    int j = base;
    for (; j + 8 <= end; j += 8) {
        int2 e[8];
        uint2 u[8];
#pragma unroll
        for (int q = 0; q < 8; q++) e[q] = __ldg(&g_csr[j + q]);
#pragma unroll
        for (int q = 0; q < 8; q++)
            u[q] = __ldg(reinterpret_cast<const uint2*>(
                       g_hg16 + (size_t)e[q].x * HDIM + lane * 4));
#pragma unroll
        for (int q = 0; q < 8; q++) {
            float n = __int_as_float(e[q].y);
            float2 f0 = __half22float2(*reinterpret_cast<__half2*>(&u[q].x));
            float2 f1 = __half22float2(*reinterpret_cast<__half2*>(&u[q].y));
            acc.x = fmaf(n, f0.x, acc.x);
            acc.y = fmaf(n, f0.y, acc.y);
            acc.z = fmaf(n, f1.x, acc.z);
            acc.w = fmaf(n, f1.y, acc.w);
        }
    }
    for (; j < end; j++) {
        int2 e = __ldg(&g_csr[j]);
        uint2 u = __ldg(reinterpret_cast<const uint2*>(
                      g_hg16 + (size_t)e.x * HDIM + lane * 4));
        float n = __int_as_float(e.y);
        float2 f0 = __half22float2(*reinterpret_cast<__half2*>(&u.x));
        float2 f1 = __half22float2(*reinterpret_cast<__half2*>(&u.y));
        acc.x = fmaf(n, f0.x, acc.x);
        acc.y = fmaf(n, f0.y, acc.y);
        acc.z = fmaf(n, f1.x, acc.z);
        acc.w = fmaf(n, f1.y, acc.w);
    }

    float4 o;
    o.x = mishf(acc.x);
    o.y = mishf(acc.y);
    o.z = mishf(acc.z);
    o.w = mishf(acc.w);

    if (LAST) {
        float4 wv = *reinterpret_cast<const float4*>(Wp + lane * 4);
        float sum = o.x * wv.x + o.y * wv.y + o.z * wv.z + o.w * wv.w;
#pragma unroll
        for (int s = 16; s > 0; s >>= 1) sum += __shfl_xor_sync(0xFFFFFFFFu, sum, s);
        if (lane == 0) out[warp] = sum + bp[0];
    } else {
        size_t fo = (size_t)warp * HDIM + lane * 4;
        bsplit(o.x, g_ahi[fo + 0], g_alo[fo + 0]);
        bsplit(o.y, g_ahi[fo + 1], g_alo[fo + 1]);
        bsplit(o.z, g_ahi[fo + 2], g_alo[fo + 2]);
        bsplit(o.w, g_ahi[fo + 3], g_alo[fo + 3]);
    }
}

// ---------------- launch ----------------
extern "C" void kernel_launch(void* const* d_in, const int* in_sizes, int n_in,
                              void* d_out, int out_size) {
    const float* x      = (const float*)d_in[0];
    const int*   ei     = (const int*)d_in[1];     // int32 (JAX x64-disabled)
    const float* W_pre  = (const float*)d_in[2];
    const float* b_pre  = (const float*)d_in[3];
    const float* gcn_W  = (const float*)d_in[4];
    const float* gcn_b  = (const float*)d_in[5];
    const float* skip_W = (const float*)d_in[6];
    const float* skip_b = (const float*)d_in[7];
    const float* W_post = (const float*)d_in[8];
    const float* b_post = (const float*)d_in[9];
    float*       out    = (float*)d_out;

    const int M = in_sizes[0] / HDIM;          // 50000
    const int E = in_sizes[1] / 2;             // 1600000
    const int L = in_sizes[4] / (HDIM * HDIM); // 3
    const int ntot = NPAD * HDIM;

    static cudaStream_t s1 = nullptr, s2 = nullptr;
    static cudaEvent_t evF1 = nullptr, evF2 = nullptr, evB = nullptr, evW = nullptr;
    if (!s1) {
        cudaStreamCreateWithFlags(&s1, cudaStreamNonBlocking);
        cudaStreamCreateWithFlags(&s2, cudaStreamNonBlocking);
        cudaEventCreateWithFlags(&evF1, cudaEventDisableTiming);
        cudaEventCreateWithFlags(&evF2, cudaEventDisableTiming);
        cudaEventCreateWithFlags(&evB, cudaEventDisableTiming);
        cudaEventCreateWithFlags(&evW, cudaEventDisableTiming);
        cudaFuncSetAttribute(wmma_gemm64<0>,
                             cudaFuncAttributeMaxDynamicSharedMemorySize, SMEM64);
        cudaFuncSetAttribute(wmma_gemm64<1>,
                             cudaFuncAttributeMaxDynamicSharedMemorySize, SMEM64);
    }

    const int TB = 256;
    const int gemm_blocks = NPAD / 64;             // 784 row tiles
    const int node_blocks = (NPAD + TB - 1) / TB;
    const int edge_blocks = (E + TB - 1) / TB;
    const int nt_blocks   = (ntot + TB - 1) / TB;
    const int w_blocks    = (HDIM * HDIM + TB - 1) / TB;
    const int aggw_blocks = (NPAD * 32) / TB;
    const int post_blocks = (M * 32 + TB - 1) / TB;

    // ---- fork: CSR build on s1, layer-weight splits on s2 ----
    cudaEventRecord(evF1, 0);
    cudaStreamWaitEvent(s1, evF1, 0);
    cudaEventRecord(evF2, 0);
    cudaStreamWaitEvent(s2, evF2, 0);

    zero_cnt_kernel<<<node_blocks, TB, 0, s1>>>(NPAD);
    count_kernel<<<edge_blocks, TB, 0, s1>>>(ei, E, M);
    scan_kernel<<<1, 1024, 0, s1>>>();
    dis_kernel<<<node_blocks, TB, 0, s1>>>(NPAD);
    scatter_kernel<<<edge_blocks, TB, 0, s1>>>(ei, E, M);
    cudaEventRecord(evB, s1);

    for (int l = 0; l < L; l++) {
        split_w_kernel<<<w_blocks, TB, 0, s2>>>(gcn_W  + (size_t)l * HDIM * HDIM, 1 + l, 0);
        split_w_kernel<<<w_blocks, TB, 0, s2>>>(skip_W + (size_t)l * HDIM * HDIM, 1 + l, 128);
    }
    cudaEventRecord(evW, s2);

    // ---- main chain on stream 0 ----
    split_w_kernel<<<w_blocks, TB>>>(W_pre, 0, 0);
    split_x_kernel<<<nt_blocks, TB>>>(x, M, ntot);
    wmma_gemm64<0><<<dim3(gemm_blocks, 1), TB, SMEM64>>>(0, b_pre);

    cudaStreamWaitEvent(0, evW, 0);    // layer weights ready
    for (int l = 0; l < L; l++) {
        const float* gb = gcn_b  + (size_t)l * HDIM;
        const float* sb = skip_b + (size_t)l * HDIM;
        wmma_gemm64<1><<<dim3(gemm_blocks, 2), TB, SMEM64>>>(1 + l, nullptr);
        if (l == 0) cudaStreamWaitEvent(0, evB, 0);   // CSR ready before first agg
        if (l == L - 1)
            csr_agg_kernel<true><<<post_blocks, TB>>>(gb, sb, W_post, b_post, out, M);
        else
            csr_agg_kernel<false><<<aggw_blocks, TB>>>(gb, sb, nullptr, nullptr, nullptr, M);
    }
}